// round 10
// baseline (speedup 1.0000x reference)
#include <cuda_runtime.h>
#include <cuda_bf16.h>
#include <cstdint>

// SegmentMM: out[i] = A[i] @ B_eff[segA[i]]
// A:[131072,64] f32, B:[128,64,64] f32, segA int32 sorted, segB int32 perm.
// bf16 3-split (Ah*Bh + Ah*Bl + Al*Bh) on HMMA m16n8k16.
// R10: L1-wavefront-bound -> amortize B smem reads: 128-row CTA, 4 warps x
// 32 rows (2 m-tiles/warp, full N). B tile LDSM'd once per 128 rows.

#define S_SEG 128

// Pre-split B, SW128-swizzled tile images, indexed by segment LABEL.
__device__ __align__(16) unsigned char d_Bh[S_SEG * 8192];
__device__ __align__(16) unsigned char d_Bl[S_SEG * 8192];

__device__ __forceinline__ uint32_t sw128(uint32_t off) {
    return off ^ ((off >> 3) & 0x70);
}

__device__ __forceinline__ void cvt_split4(float4 v, uint2& hi, uint2& lo) {
    __nv_bfloat162 h01 = __floats2bfloat162_rn(v.x, v.y);
    __nv_bfloat162 h23 = __floats2bfloat162_rn(v.z, v.w);
    float rx = v.x - __bfloat162float(h01.x);
    float ry = v.y - __bfloat162float(h01.y);
    float rz = v.z - __bfloat162float(h23.x);
    float rw = v.w - __bfloat162float(h23.y);
    __nv_bfloat162 l01 = __floats2bfloat162_rn(rx, ry);
    __nv_bfloat162 l23 = __floats2bfloat162_rn(rz, rw);
    hi = make_uint2(*(uint32_t*)&h01, *(uint32_t*)&h23);
    lo = make_uint2(*(uint32_t*)&l01, *(uint32_t*)&l23);
}

__device__ __forceinline__ void cvt_split2(float2 v, uint32_t& hi, uint32_t& lo) {
    __nv_bfloat162 h = __floats2bfloat162_rn(v.x, v.y);
    float rx = v.x - __bfloat162float(h.x);
    float ry = v.y - __bfloat162float(h.y);
    __nv_bfloat162 l = __floats2bfloat162_rn(rx, ry);
    hi = *(uint32_t*)&h;
    lo = *(uint32_t*)&l;
}

// ---- B pre-split kernel: block j converts B[j] -> d_Bh/d_Bl[segB[j]] ----
__global__ __launch_bounds__(256)
void presplit_B_kernel(const float* __restrict__ B,
                       const int* __restrict__ segB)
{
    const int j = blockIdx.x;
    const int s = segB[j];
    const int tid = threadIdx.x;
    const float4* B4 = (const float4*)(B + (size_t)j * 4096);
    unsigned char* bh = d_Bh + (size_t)s * 8192;
    unsigned char* bl = d_Bl + (size_t)s * 8192;
    #pragma unroll
    for (int it = 0; it < 4; ++it) {
        int i = it * 256 + tid;          // 0..1023 float4s
        float4 v = B4[i];
        int k = i >> 4, mq = i & 15;
        uint32_t sw = sw128((uint32_t)(k * 128 + mq * 8));
        uint2 hi, lo;
        cvt_split4(v, hi, lo);
        *(uint2*)(bh + sw) = hi;
        *(uint2*)(bl + sw) = lo;
    }
}

// ---- main kernel ----
// smem: A f32 128 rows x 272B pitch = 34816B, then Bh/Bl SW128 (8KB each).
#define A_PITCH_B 272
#define SM_AF  0
#define SM_BH  34816
#define SM_BL  (34816 + 8192)
#define SMEM_TOTAL (34816 + 16384)

__device__ __forceinline__ uint32_t smem_u32(const void* p) {
    uint32_t a;
    asm("{ .reg .u64 t; cvta.to.shared.u64 t, %1; cvt.u32.u64 %0, t; }"
        : "=r"(a) : "l"(p));
    return a;
}
__device__ __forceinline__ void ldsm_x4t(uint32_t& r0, uint32_t& r1,
                                         uint32_t& r2, uint32_t& r3, uint32_t a) {
    asm volatile("ldmatrix.sync.aligned.m8n8.x4.trans.shared.b16 {%0,%1,%2,%3}, [%4];"
                 : "=r"(r0), "=r"(r1), "=r"(r2), "=r"(r3) : "r"(a));
}
__device__ __forceinline__ void mma16816(float* d, const uint32_t* a,
                                         uint32_t b0, uint32_t b1) {
    asm volatile(
        "mma.sync.aligned.m16n8k16.row.col.f32.bf16.bf16.f32 "
        "{%0,%1,%2,%3}, {%4,%5,%6,%7}, {%8,%9}, {%0,%1,%2,%3};"
        : "+f"(d[0]), "+f"(d[1]), "+f"(d[2]), "+f"(d[3])
        : "r"(a[0]), "r"(a[1]), "r"(a[2]), "r"(a[3]), "r"(b0), "r"(b1));
}
#define CP_ASYNC16(dst, src)                                                   \
    asm volatile("cp.async.cg.shared.global [%0], [%1], 16;"                   \
                 :: "r"(dst), "l"(src) : "memory")
#define CP_COMMIT  asm volatile("cp.async.commit_group;" ::: "memory")
#define CP_WAIT0   asm volatile("cp.async.wait_group 0;" ::: "memory")

__global__ __launch_bounds__(128, 4)
void segmm_hmma_kernel(const float* __restrict__ A,
                       const int* __restrict__ segA,
                       float* __restrict__ out)
{
    extern __shared__ __align__(128) unsigned char smem[];
    const uint32_t sb  = smem_u32(smem);
    const int tid  = threadIdx.x;
    const int w    = tid >> 5;          // warp 0..3, owns rows w*32..w*32+31
    const int lane = tid & 31;
    const int r0   = blockIdx.x * 128;

    const int rA = w * 32 + (lane >> 2);  // rows rA, rA+8 (m0), rA+16, rA+24 (m1)
    const int cb = (lane & 3) * 2;
    const int seg0 = segA[r0 + rA];
    const int seg1 = segA[r0 + rA + 8];
    const int seg2 = segA[r0 + rA + 16];
    const int seg3 = segA[r0 + rA + 24];
    const int s_lo = segA[r0];
    const int s_hi = segA[r0 + 127];

    // ---- cp.async: A f32 tile (128 rows) + B(s_lo), one group, one wait ----
    {
        const unsigned char* gA = (const unsigned char*)(A + (size_t)r0 * 64);
        #pragma unroll
        for (int it = 0; it < 16; ++it) {
            int i = it * 128 + tid;          // 0..2047 16B-chunks
            int r = i >> 4, c = i & 15;
            CP_ASYNC16(sb + SM_AF + (uint32_t)(r * A_PITCH_B + c * 16),
                       gA + (size_t)r * 256 + c * 16);
        }
        const unsigned char* gh = d_Bh + (size_t)s_lo * 8192;
        const unsigned char* gl = d_Bl + (size_t)s_lo * 8192;
        #pragma unroll
        for (int it = 0; it < 4; ++it) {
            uint32_t off = (uint32_t)(it * 128 + tid) * 16;
            CP_ASYNC16(sb + SM_BH + off, gh + off);
            CP_ASYNC16(sb + SM_BL + off, gl + off);
        }
        CP_COMMIT;
    }
    CP_WAIT0;
    __syncthreads();

    // A fragment smem byte addresses for both m-tiles (f32, padded pitch)
    const uint32_t a00 = sb + SM_AF + (uint32_t)rA * A_PITCH_B + (uint32_t)cb * 4;
    const uint32_t a01 = a00 + 8 * A_PITCH_B;
    const uint32_t a10 = a00 + 16 * A_PITCH_B;
    const uint32_t a11 = a00 + 24 * A_PITCH_B;

    const uint32_t b_row = (uint32_t)(lane & 15);
    const uint32_t b_nt  = (uint32_t)(lane >> 4);   // 0 or 1

    for (int s = s_lo; s <= s_hi; ++s) {
        if (s > s_lo) {
            __syncthreads();   // everyone done reading previous B
            const unsigned char* gh = d_Bh + (size_t)s * 8192;
            const unsigned char* gl = d_Bl + (size_t)s * 8192;
            #pragma unroll
            for (int it = 0; it < 4; ++it) {
                uint32_t off = (uint32_t)(it * 128 + tid) * 16;
                CP_ASYNC16(sb + SM_BH + off, gh + off);
                CP_ASYNC16(sb + SM_BL + off, gl + off);
            }
            CP_COMMIT;
            CP_WAIT0;
            __syncthreads();
        }

        bool ok0 = (seg0 == s), ok1 = (seg1 == s);
        bool ok2 = (seg2 == s), ok3 = (seg3 == s);
        if (__ballot_sync(0xffffffffu, ok0 || ok1 || ok2 || ok3) == 0u) continue;

        float acc[2][8][4];
        #pragma unroll
        for (int m = 0; m < 2; ++m)
            #pragma unroll
            for (int nt = 0; nt < 8; ++nt)
                #pragma unroll
                for (int q = 0; q < 4; ++q) acc[m][nt][q] = 0.f;

        #pragma unroll
        for (int kk = 0; kk < 4; ++kk) {
            // gather A fragments for both m-tiles, split in registers
            uint32_t ahf[2][4], alf[2][4];
            {
                float2 v0, v1, v2, v3;
                asm volatile("ld.shared.v2.f32 {%0,%1}, [%2];"
                             : "=f"(v0.x), "=f"(v0.y) : "r"(a00 + kk * 64));
                asm volatile("ld.shared.v2.f32 {%0,%1}, [%2];"
                             : "=f"(v1.x), "=f"(v1.y) : "r"(a01 + kk * 64));
                asm volatile("ld.shared.v2.f32 {%0,%1}, [%2];"
                             : "=f"(v2.x), "=f"(v2.y) : "r"(a00 + kk * 64 + 32));
                asm volatile("ld.shared.v2.f32 {%0,%1}, [%2];"
                             : "=f"(v3.x), "=f"(v3.y) : "r"(a01 + kk * 64 + 32));
                cvt_split2(v0, ahf[0][0], alf[0][0]);
                cvt_split2(v1, ahf[0][1], alf[0][1]);
                cvt_split2(v2, ahf[0][2], alf[0][2]);
                cvt_split2(v3, ahf[0][3], alf[0][3]);
                asm volatile("ld.shared.v2.f32 {%0,%1}, [%2];"
                             : "=f"(v0.x), "=f"(v0.y) : "r"(a10 + kk * 64));
                asm volatile("ld.shared.v2.f32 {%0,%1}, [%2];"
                             : "=f"(v1.x), "=f"(v1.y) : "r"(a11 + kk * 64));
                asm volatile("ld.shared.v2.f32 {%0,%1}, [%2];"
                             : "=f"(v2.x), "=f"(v2.y) : "r"(a10 + kk * 64 + 32));
                asm volatile("ld.shared.v2.f32 {%0,%1}, [%2];"
                             : "=f"(v3.x), "=f"(v3.y) : "r"(a11 + kk * 64 + 32));
                cvt_split2(v0, ahf[1][0], alf[1][0]);
                cvt_split2(v1, ahf[1][1], alf[1][1]);
                cvt_split2(v2, ahf[1][2], alf[1][2]);
                cvt_split2(v3, ahf[1][3], alf[1][3]);
            }

            uint32_t roff = ((uint32_t)(kk * 16) + b_row) * 128;
            #pragma unroll
            for (int ntp = 0; ntp < 4; ++ntp) {
                uint32_t sw = sw128(roff + ((uint32_t)(ntp * 2) + b_nt) * 16);
                uint32_t bh0, bh1, bh2, bh3, bl0, bl1, bl2, bl3;
                ldsm_x4t(bh0, bh1, bh2, bh3, sb + SM_BH + sw);
                ldsm_x4t(bl0, bl1, bl2, bl3, sb + SM_BL + sw);
                // two independent m-tile chains interleaved
                mma16816(acc[0][ntp * 2],     ahf[0], bh0, bh1);
                mma16816(acc[1][ntp * 2],     ahf[1], bh0, bh1);
                mma16816(acc[0][ntp * 2],     ahf[0], bl0, bl1);
                mma16816(acc[1][ntp * 2],     ahf[1], bl0, bl1);
                mma16816(acc[0][ntp * 2],     alf[0], bh0, bh1);
                mma16816(acc[1][ntp * 2],     alf[1], bh0, bh1);
                mma16816(acc[0][ntp * 2 + 1], ahf[0], bh2, bh3);
                mma16816(acc[1][ntp * 2 + 1], ahf[1], bh2, bh3);
                mma16816(acc[0][ntp * 2 + 1], ahf[0], bl2, bl3);
                mma16816(acc[1][ntp * 2 + 1], ahf[1], bl2, bl3);
                mma16816(acc[0][ntp * 2 + 1], alf[0], bh2, bh3);
                mma16816(acc[1][ntp * 2 + 1], alf[1], bh2, bh3);
            }
        }

        // ---- store rows belonging to segment s ----
        float* o0 = out + (size_t)(r0 + rA) * 64 + cb;
        float* o1 = o0 + 8 * 64;
        float* o2 = o0 + 16 * 64;
        float* o3 = o0 + 24 * 64;
        #pragma unroll
        for (int nt = 0; nt < 8; ++nt) {
            if (ok0) *(float2*)(o0 + nt * 8) = make_float2(acc[0][nt][0], acc[0][nt][1]);
            if (ok1) *(float2*)(o1 + nt * 8) = make_float2(acc[0][nt][2], acc[0][nt][3]);
            if (ok2) *(float2*)(o2 + nt * 8) = make_float2(acc[1][nt][0], acc[1][nt][1]);
            if (ok3) *(float2*)(o3 + nt * 8) = make_float2(acc[1][nt][2], acc[1][nt][3]);
        }
    }
}

extern "C" void kernel_launch(void* const* d_in, const int* in_sizes, int n_in,
                              void* d_out, int out_size) {
    const float* A    = (const float*)d_in[0];
    const float* B    = (const float*)d_in[1];
    const int*   segA = (const int*)d_in[2];
    const int*   segB = (const int*)d_in[3];
    float* out = (float*)d_out;

    const int N = in_sizes[0] / 64;      // 131072
    const int S = in_sizes[3];           // 128

    cudaFuncSetAttribute(segmm_hmma_kernel,
                         cudaFuncAttributeMaxDynamicSharedMemorySize, SMEM_TOTAL);

    presplit_B_kernel<<<S, 256>>>(B, segB);
    segmm_hmma_kernel<<<N / 128, 128, SMEM_TOTAL>>>(A, segA, out);
}

// round 11
// speedup vs baseline: 1.1396x; 1.1396x over previous
#include <cuda_runtime.h>
#include <cuda_bf16.h>
#include <cstdint>

// SegmentMM: out[i] = A[i] @ B_eff[segA[i]]
// A:[131072,64] f32, B:[128,64,64] f32, segA int32 sorted, segB int32 perm.
// bf16 3-split (Ah*Bh + Ah*Bl + Al*Bh) on HMMA m16n8k16.
// R11: 256 thr / 64-row CTA; A staged ONCE cooperatively as bf16 SW128 smem,
// consumed via ldmatrix x4 (high MMA density); warps split N (4 ntiles each);
// B presplit + cp.async. 64 regs -> 4 CTA/SM, 32 warps.

#define S_SEG 128

__device__ __align__(16) unsigned char d_Bh[S_SEG * 8192];
__device__ __align__(16) unsigned char d_Bl[S_SEG * 8192];

__device__ __forceinline__ uint32_t sw128(uint32_t off) {
    return off ^ ((off >> 3) & 0x70);
}

__device__ __forceinline__ void cvt_split4(float4 v, uint2& hi, uint2& lo) {
    __nv_bfloat162 h01 = __floats2bfloat162_rn(v.x, v.y);
    __nv_bfloat162 h23 = __floats2bfloat162_rn(v.z, v.w);
    float rx = v.x - __bfloat162float(h01.x);
    float ry = v.y - __bfloat162float(h01.y);
    float rz = v.z - __bfloat162float(h23.x);
    float rw = v.w - __bfloat162float(h23.y);
    __nv_bfloat162 l01 = __floats2bfloat162_rn(rx, ry);
    __nv_bfloat162 l23 = __floats2bfloat162_rn(rz, rw);
    hi = make_uint2(*(uint32_t*)&h01, *(uint32_t*)&h23);
    lo = make_uint2(*(uint32_t*)&l01, *(uint32_t*)&l23);
}

// ---- B pre-split kernel ----
__global__ __launch_bounds__(256)
void presplit_B_kernel(const float* __restrict__ B,
                       const int* __restrict__ segB)
{
    const int j = blockIdx.x;
    const int s = segB[j];
    const int tid = threadIdx.x;
    const float4* B4 = (const float4*)(B + (size_t)j * 4096);
    unsigned char* bh = d_Bh + (size_t)s * 8192;
    unsigned char* bl = d_Bl + (size_t)s * 8192;
    #pragma unroll
    for (int it = 0; it < 4; ++it) {
        int i = it * 256 + tid;
        float4 v = B4[i];
        int k = i >> 4, mq = i & 15;
        uint32_t sw = sw128((uint32_t)(k * 128 + mq * 8));
        uint2 hi, lo;
        cvt_split4(v, hi, lo);
        *(uint2*)(bh + sw) = hi;
        *(uint2*)(bl + sw) = lo;
    }
}

// ---- main kernel smem: Ah/Al/Bh/Bl, each 64x64 bf16 SW128 = 8KB ----
#define SM_AH 0
#define SM_AL 8192
#define SM_BH 16384
#define SM_BL 24576
#define SMEM_TOTAL 32768

__device__ __forceinline__ uint32_t smem_u32(const void* p) {
    uint32_t a;
    asm("{ .reg .u64 t; cvta.to.shared.u64 t, %1; cvt.u32.u64 %0, t; }"
        : "=r"(a) : "l"(p));
    return a;
}
__device__ __forceinline__ void ldsm_x4(uint32_t& r0, uint32_t& r1,
                                        uint32_t& r2, uint32_t& r3, uint32_t a) {
    asm volatile("ldmatrix.sync.aligned.m8n8.x4.shared.b16 {%0,%1,%2,%3}, [%4];"
                 : "=r"(r0), "=r"(r1), "=r"(r2), "=r"(r3) : "r"(a));
}
__device__ __forceinline__ void ldsm_x4t(uint32_t& r0, uint32_t& r1,
                                         uint32_t& r2, uint32_t& r3, uint32_t a) {
    asm volatile("ldmatrix.sync.aligned.m8n8.x4.trans.shared.b16 {%0,%1,%2,%3}, [%4];"
                 : "=r"(r0), "=r"(r1), "=r"(r2), "=r"(r3) : "r"(a));
}
__device__ __forceinline__ void mma16816(float* d, const uint32_t* a,
                                         uint32_t b0, uint32_t b1) {
    asm volatile(
        "mma.sync.aligned.m16n8k16.row.col.f32.bf16.bf16.f32 "
        "{%0,%1,%2,%3}, {%4,%5,%6,%7}, {%8,%9}, {%0,%1,%2,%3};"
        : "+f"(d[0]), "+f"(d[1]), "+f"(d[2]), "+f"(d[3])
        : "r"(a[0]), "r"(a[1]), "r"(a[2]), "r"(a[3]), "r"(b0), "r"(b1));
}
#define CP_ASYNC16(dst, src)                                                   \
    asm volatile("cp.async.cg.shared.global [%0], [%1], 16;"                   \
                 :: "r"(dst), "l"(src) : "memory")
#define CP_COMMIT  asm volatile("cp.async.commit_group;" ::: "memory")
#define CP_WAIT0   asm volatile("cp.async.wait_group 0;" ::: "memory")

__global__ __launch_bounds__(256, 4)
void segmm_hmma_kernel(const float* __restrict__ A,
                       const int* __restrict__ segA,
                       float* __restrict__ out)
{
    __shared__ __align__(128) unsigned char smem[SMEM_TOTAL];
    const uint32_t sb  = smem_u32(smem);
    const int tid   = threadIdx.x;
    const int w     = tid >> 5;          // 0..7
    const int lane  = tid & 31;
    const int r0    = blockIdx.x * 64;
    const int wrow  = (w & 3) * 16;      // row group
    const int whalf = (w >> 2);          // N half: ntiles whalf*4..+3

    const int rA = wrow + (lane >> 2);
    const int rB = rA + 8;
    const int cb = (lane & 3) * 2;
    const int seg0 = segA[r0 + rA];
    const int seg1 = segA[r0 + rB];
    const int s_lo = segA[r0];
    const int s_hi = segA[r0 + 63];

    // ---- B(s_lo) cp.async first (overlaps A phase) ----
    {
        const unsigned char* gh = d_Bh + (size_t)s_lo * 8192;
        const unsigned char* gl = d_Bl + (size_t)s_lo * 8192;
        #pragma unroll
        for (int it = 0; it < 2; ++it) {
            uint32_t off = (uint32_t)(it * 256 + tid) * 16;
            CP_ASYNC16(sb + SM_BH + off, gh + off);
            CP_ASYNC16(sb + SM_BL + off, gl + off);
        }
        CP_COMMIT;
    }

    // ---- stage A once: f32 -> Ah/Al bf16 SW128 smem (cooperative) ----
    {
        const float4* A4 = (const float4*)(A + (size_t)r0 * 64);
        #pragma unroll
        for (int it = 0; it < 4; ++it) {
            int i = it * 256 + tid;          // 0..1023 float4s
            float4 v = A4[i];
            int r = i >> 4, kq = i & 15;
            uint32_t sw = sw128((uint32_t)(r * 128 + kq * 8));
            uint2 hi, lo;
            cvt_split4(v, hi, lo);
            *(uint2*)(smem + SM_AH + sw) = hi;
            *(uint2*)(smem + SM_AL + sw) = lo;
        }
    }
    CP_WAIT0;
    __syncthreads();

    // ldmatrix lane address components
    const uint32_t a_row = (uint32_t)(wrow + (lane & 15));
    const uint32_t a_sel = (uint32_t)(lane >> 4) * 16;   // k-halve within kstep
    const uint32_t b_row = (uint32_t)(lane & 15);
    const uint32_t b_nt  = (uint32_t)(lane >> 4);        // 0/1
    const uint32_t ntb   = (uint32_t)whalf * 4;          // ntile base

    for (int s = s_lo; s <= s_hi; ++s) {
        if (s > s_lo) {
            __syncthreads();
            const unsigned char* gh = d_Bh + (size_t)s * 8192;
            const unsigned char* gl = d_Bl + (size_t)s * 8192;
            #pragma unroll
            for (int it = 0; it < 2; ++it) {
                uint32_t off = (uint32_t)(it * 256 + tid) * 16;
                CP_ASYNC16(sb + SM_BH + off, gh + off);
                CP_ASYNC16(sb + SM_BL + off, gl + off);
            }
            CP_COMMIT;
            CP_WAIT0;
            __syncthreads();
        }

        bool ok0 = (seg0 == s);
        bool ok1 = (seg1 == s);
        if (__ballot_sync(0xffffffffu, ok0 || ok1) == 0u) continue;

        float acc[4][4];
        #pragma unroll
        for (int nt = 0; nt < 4; ++nt)
            #pragma unroll
            for (int q = 0; q < 4; ++q) acc[nt][q] = 0.f;

        #pragma unroll
        for (int kk = 0; kk < 4; ++kk) {
            // A fragments via ldmatrix x4 (hi and lo)
            uint32_t asw = sw128(a_row * 128 + (uint32_t)(kk * 32) + a_sel);
            uint32_t ah[4], al[4];
            ldsm_x4(ah[0], ah[1], ah[2], ah[3], sb + SM_AH + asw);
            ldsm_x4(al[0], al[1], al[2], al[3], sb + SM_AL + asw);

            uint32_t roff = ((uint32_t)(kk * 16) + b_row) * 128;
            #pragma unroll
            for (int ntp = 0; ntp < 2; ++ntp) {
                uint32_t sw = sw128(roff + (ntb + (uint32_t)(ntp * 2) + b_nt) * 16);
                uint32_t bh0, bh1, bh2, bh3, bl0, bl1, bl2, bl3;
                ldsm_x4t(bh0, bh1, bh2, bh3, sb + SM_BH + sw);
                ldsm_x4t(bl0, bl1, bl2, bl3, sb + SM_BL + sw);
                mma16816(acc[ntp * 2],     ah, bh0, bh1);
                mma16816(acc[ntp * 2 + 1], ah, bh2, bh3);
                mma16816(acc[ntp * 2],     ah, bl0, bl1);
                mma16816(acc[ntp * 2 + 1], ah, bl2, bl3);
                mma16816(acc[ntp * 2],     al, bh0, bh1);
                mma16816(acc[ntp * 2 + 1], al, bh2, bh3);
            }
        }

        // ---- store rows belonging to segment s (warp's 32-col half) ----
        float* o0 = out + (size_t)(r0 + rA) * 64 + whalf * 32 + cb;
        float* o1 = out + (size_t)(r0 + rB) * 64 + whalf * 32 + cb;
        #pragma unroll
        for (int nt = 0; nt < 4; ++nt) {
            if (ok0) *(float2*)(o0 + nt * 8) = make_float2(acc[nt][0], acc[nt][1]);
            if (ok1) *(float2*)(o1 + nt * 8) = make_float2(acc[nt][2], acc[nt][3]);
        }
    }
}

extern "C" void kernel_launch(void* const* d_in, const int* in_sizes, int n_in,
                              void* d_out, int out_size) {
    const float* A    = (const float*)d_in[0];
    const float* B    = (const float*)d_in[1];
    const int*   segA = (const int*)d_in[2];
    const int*   segB = (const int*)d_in[3];
    float* out = (float*)d_out;

    const int N = in_sizes[0] / 64;      // 131072
    const int S = in_sizes[3];           // 128

    presplit_B_kernel<<<S, 256>>>(B, segB);
    segmm_hmma_kernel<<<N / 64, 256>>>(A, segA, out);
}